// round 1
// baseline (speedup 1.0000x reference)
#include <cuda_runtime.h>
#include <cuda_bf16.h>

// RNNModel: T=512, B=256, I=256, H=512, fp32.
//   K1: xp[t,b,h] = sum_i x[t,b,i]*w_ih[h,i] + b_ih[h] + b_hh[h]
//   K2: h_t = tanh(xp_t + h_{t-1} @ w_hh^T)   (serial over t, persistent kernel)
//   K3: out[t,b,o] = sum_h hs[t,b,h]*w_fc[o,h] + b_fc[o]
// All math fp32, inner loops use packed fma.rn.f32x2 (2x FFMA throughput on sm_103a).

#define T_ 512
#define B_ 256
#define I_ 256
#define H_ 512

#define NG  16   // batch groups
#define NSL 8    // H slices per group
#define BT  16   // batch rows per group (B_/NG)
#define NS  64   // H columns per slice (H_/NSL)
#define WPAD 68  // padded row stride for w_t[k][n] (16B aligned, conflict-light)

// Scratch (device globals; no runtime allocation allowed)
__device__ float g_xp[(size_t)T_ * B_ * H_];  // 256 MB
__device__ float g_hs[(size_t)T_ * B_ * H_];  // 256 MB
__device__ int   g_cnt[NG];

// ---------------- f32x2 helpers ----------------
__device__ __forceinline__ unsigned long long f32x2_fma(unsigned long long a,
                                                        unsigned long long b,
                                                        unsigned long long c) {
    unsigned long long d;
    asm("fma.rn.f32x2 %0, %1, %2, %3;" : "=l"(d) : "l"(a), "l"(b), "l"(c));
    return d;
}
__device__ __forceinline__ unsigned long long f32x2_splat(float x) {
    unsigned long long d;
    unsigned int xi = __float_as_uint(x);
    asm("mov.b64 %0, {%1, %1};" : "=l"(d) : "r"(xi));
    return d;
}
__device__ __forceinline__ float2 f32x2_unpack(unsigned long long v) {
    unsigned int lo, hi;
    asm("mov.b64 {%0, %1}, %2;" : "=r"(lo), "=r"(hi) : "l"(v));
    float2 r;
    r.x = __uint_as_float(lo);
    r.y = __uint_as_float(hi);
    return r;
}

// ---------------- init ----------------
__global__ void zero_cnt_kernel() {
    if (threadIdx.x < NG) g_cnt[threadIdx.x] = 0;
}

// ---------------- K1/K3: C[M,N] = A[M,K] * B[N,K]^T + bias1[n] (+bias2[n]) ----------------
// CTA tile 128x128, K-tile 8, 256 threads, 8x8 per thread (f32x2-packed along n).
__global__ void __launch_bounds__(256) sgemm_bias_kernel(
    const float* __restrict__ A, const float* __restrict__ Bm,
    const float* __restrict__ b1, const float* __restrict__ b2,
    float* __restrict__ C, int M, int N, int K)
{
    __shared__ __align__(16) float As[8 * 128];
    __shared__ __align__(16) float Bs[8 * 128];

    const int tid = threadIdx.x;
    const int m0 = blockIdx.y * 128;
    const int n0 = blockIdx.x * 128;

    // global->smem loaders: 256 threads, each loads one float4 of A and B per k-tile
    const int lr = tid >> 1;          // row within tile (0..127)
    const int lc = (tid & 1) << 2;    // k offset (0 or 4)
    const float* Ap = A + (size_t)(m0 + lr) * K + lc;
    const float* Bp = Bm + (size_t)(n0 + lr) * K + lc;

    const int tx = tid & 15;          // n tile (8 cols)
    const int ty = tid >> 4;          // m tile (8 rows)

    unsigned long long acc[8][4];
#pragma unroll
    for (int i = 0; i < 8; i++)
#pragma unroll
        for (int j = 0; j < 4; j++) acc[i][j] = 0ull;

    float4 av = *(const float4*)Ap;
    float4 bv = *(const float4*)Bp;

    for (int kt = 0; kt < K; kt += 8) {
        As[(lc + 0) * 128 + lr] = av.x;
        As[(lc + 1) * 128 + lr] = av.y;
        As[(lc + 2) * 128 + lr] = av.z;
        As[(lc + 3) * 128 + lr] = av.w;
        Bs[(lc + 0) * 128 + lr] = bv.x;
        Bs[(lc + 1) * 128 + lr] = bv.y;
        Bs[(lc + 2) * 128 + lr] = bv.z;
        Bs[(lc + 3) * 128 + lr] = bv.w;
        __syncthreads();

        if (kt + 8 < K) {  // prefetch next tile while computing
            av = *(const float4*)(Ap + kt + 8);
            bv = *(const float4*)(Bp + kt + 8);
        }

#pragma unroll
        for (int k = 0; k < 8; k++) {
            float4 a0 = *(const float4*)&As[k * 128 + ty * 8];
            float4 a1 = *(const float4*)&As[k * 128 + ty * 8 + 4];
            ulonglong2 w0 = *(const ulonglong2*)&Bs[k * 128 + tx * 8];
            ulonglong2 w1 = *(const ulonglong2*)&Bs[k * 128 + tx * 8 + 4];
            float aarr[8] = {a0.x, a0.y, a0.z, a0.w, a1.x, a1.y, a1.z, a1.w};
            unsigned long long wv[4] = {w0.x, w0.y, w1.x, w1.y};
#pragma unroll
            for (int i = 0; i < 8; i++) {
                unsigned long long s = f32x2_splat(aarr[i]);
#pragma unroll
                for (int j = 0; j < 4; j++)
                    acc[i][j] = f32x2_fma(s, wv[j], acc[i][j]);
            }
        }
        __syncthreads();
    }

    // epilogue: add bias, write
    float bias[8];
#pragma unroll
    for (int j = 0; j < 8; j++) {
        int col = n0 + tx * 8 + j;
        float bb = b1[col];
        if (b2) bb += b2[col];
        bias[j] = bb;
    }
#pragma unroll
    for (int i = 0; i < 8; i++) {
        float o[8];
#pragma unroll
        for (int j = 0; j < 4; j++) {
            float2 v = f32x2_unpack(acc[i][j]);
            o[2 * j + 0] = v.x + bias[2 * j + 0];
            o[2 * j + 1] = v.y + bias[2 * j + 1];
        }
        float4* cp = (float4*)&C[(size_t)(m0 + ty * 8 + i) * N + n0 + tx * 8];
        cp[0] = make_float4(o[0], o[1], o[2], o[3]);
        cp[1] = make_float4(o[4], o[5], o[6], o[7]);
    }
}

// ---------------- K2: persistent recurrence ----------------
// grid = 128 CTAs = 16 batch-groups x 8 H-slices; 1 CTA/SM (204.8KB smem) => all co-resident.
// Per CTA: w_hh slice [512][64] cached in SMEM (transposed, padded); h k-major tile in SMEM.
// 8 warps split K=512; partial sums reduced in SMEM; group barrier via monotone counter.
__global__ void __launch_bounds__(256) rnn_rec_kernel(const float* __restrict__ w_hh)
{
    extern __shared__ float sm[];
    float* w_t  = sm;                        // [H_][WPAD]   (k-major w slice)
    float* hT   = sm + H_ * WPAD;            // [H_][BT]     (k-major h tile)
    float* part = hT + H_ * BT;              // [8][BT*NS]   (per-warp partials)

    const int tid = threadIdx.x;
    const int g = blockIdx.x >> 3;   // batch group
    const int s = blockIdx.x & 7;    // H slice
    const int n0 = s * NS;
    const int b0 = g * BT;

    // load w slice once: w_t[k][n] = w_hh[n0+n][k]
    for (int i = tid; i < NS * H_; i += 256) {
        int n = i >> 9;          // i / 512
        int k = i & (H_ - 1);
        w_t[k * WPAD + n] = w_hh[(size_t)(n0 + n) * H_ + k];
    }

    const int wid = tid >> 5, lane = tid & 31;
    const int bg = lane >> 3;    // 0..3 -> 4 batch rows each
    const int ng = lane & 7;     // 0..7 -> 8 n cols each
    const int k0 = wid * 64;     // per-warp K chunk

    __syncthreads();

    for (int t = 0; t < T_; t++) {
        // --- acquire: wait for all 8 slices of step t-1 ---
        if (t > 0) {
            if (tid == 0) {
                volatile int* c = g_cnt + g;
                while (*c < NSL * t) __nanosleep(40);
                __threadfence();
            }
            __syncthreads();
            const float* hsrc = g_hs + ((size_t)(t - 1) * B_ + b0) * H_;
            for (int i = tid; i < BT * H_; i += 256) {
                int b = i >> 9;
                int k = i & (H_ - 1);
                hT[k * BT + b] = hsrc[i];
            }
        } else {
            for (int i = tid; i < BT * H_; i += 256) hT[i] = 0.0f;
        }
        __syncthreads();

        // --- compute partial c[16][64] for this warp's K chunk ---
        unsigned long long acc[4][4];
#pragma unroll
        for (int b = 0; b < 4; b++)
#pragma unroll
            for (int j = 0; j < 4; j++) acc[b][j] = 0ull;

#pragma unroll 4
        for (int kk = 0; kk < 64; kk++) {
            int k = k0 + kk;
            float4 hv = *(const float4*)&hT[k * BT + bg * 4];
            ulonglong2 w0 = *(const ulonglong2*)&w_t[k * WPAD + ng * 8];
            ulonglong2 w1 = *(const ulonglong2*)&w_t[k * WPAD + ng * 8 + 4];
            float hh[4] = {hv.x, hv.y, hv.z, hv.w};
            unsigned long long wv[4] = {w0.x, w0.y, w1.x, w1.y};
#pragma unroll
            for (int b = 0; b < 4; b++) {
                unsigned long long hs2 = f32x2_splat(hh[b]);
#pragma unroll
                for (int j = 0; j < 4; j++)
                    acc[b][j] = f32x2_fma(hs2, wv[j], acc[b][j]);
            }
        }

        // --- write warp partials ---
        {
            float* pw = part + wid * (BT * NS);
#pragma unroll
            for (int b = 0; b < 4; b++) {
                int r = (bg * 4 + b) * NS + ng * 8;
                ulonglong2 q0; q0.x = acc[b][0]; q0.y = acc[b][1];
                ulonglong2 q1; q1.x = acc[b][2]; q1.y = acc[b][3];
                *(ulonglong2*)&pw[r]     = q0;
                *(ulonglong2*)&pw[r + 4] = q1;
            }
        }
        __syncthreads();

        // --- reduce 8 warps, add xp, tanh, write h_t ---
        {
            int o = tid * 4;                // covers all BT*NS = 1024 outputs
            float4 sum = *(const float4*)&part[o];
#pragma unroll
            for (int w = 1; w < 8; w++) {
                float4 p = *(const float4*)&part[w * (BT * NS) + o];
                sum.x += p.x; sum.y += p.y; sum.z += p.z; sum.w += p.w;
            }
            int b = o >> 6;
            int n = o & (NS - 1);
            size_t gidx = ((size_t)t * B_ + b0 + b) * H_ + n0 + n;
            float4 xv = *(const float4*)&g_xp[gidx];
            float4 r;
            r.x = tanhf(sum.x + xv.x);
            r.y = tanhf(sum.y + xv.y);
            r.z = tanhf(sum.z + xv.z);
            r.w = tanhf(sum.w + xv.w);
            *(float4*)&g_hs[gidx] = r;
        }
        __syncthreads();

        // --- release: publish this slice of step t ---
        if (tid == 0) {
            __threadfence();
            atomicAdd(&g_cnt[g], 1);
        }
    }
}

// ---------------- launch ----------------
extern "C" void kernel_launch(void* const* d_in, const int* in_sizes, int n_in,
                              void* d_out, int out_size)
{
    const float* x    = (const float*)d_in[0];
    const float* w_ih = (const float*)d_in[1];
    const float* w_hh = (const float*)d_in[2];
    const float* b_ih = (const float*)d_in[3];
    const float* b_hh = (const float*)d_in[4];
    const float* w_fc = (const float*)d_in[5];
    const float* b_fc = (const float*)d_in[6];
    float* out = (float*)d_out;

    float* xp = nullptr;
    float* hs = nullptr;
    cudaGetSymbolAddress((void**)&xp, g_xp);
    cudaGetSymbolAddress((void**)&hs, g_hs);

    const int rec_smem = (H_ * WPAD + H_ * BT + 8 * BT * NS) * (int)sizeof(float); // 204800
    cudaFuncSetAttribute(rnn_rec_kernel, cudaFuncAttributeMaxDynamicSharedMemorySize, rec_smem);

    const int M = T_ * B_;

    zero_cnt_kernel<<<1, 32>>>();

    // K1: xp = x @ w_ih^T + (b_ih + b_hh)
    sgemm_bias_kernel<<<dim3(H_ / 128, M / 128), 256>>>(x, w_ih, b_ih, b_hh, xp, M, H_, I_);

    // K2: recurrence (persistent, 128 CTAs)
    rnn_rec_kernel<<<NG * NSL, 256, rec_smem>>>(w_hh);

    // K3: out = hs @ w_fc^T + b_fc
    sgemm_bias_kernel<<<dim3(I_ / 128, M / 128), 256>>>(hs, w_fc, b_fc, nullptr, out, M, I_, H_);
}